// round 6
// baseline (speedup 1.0000x reference)
#include <cuda_runtime.h>
#include <cuda_fp16.h>
#include <math.h>
#include <stdint.h>

#define BB   8
#define WLEN 1000
#define EMB  100
#define CC   50
#define LL   18000

#define KPP  32      // padded k-pairs rows (k padded 50 -> 64; only 0..24 written)
#define WPAD 1024    // padded w words per row (32 chunks x 32)

// zero-initialized device globals; padding rows/words stay zero forever.
// layout: [b][kp][ch*32 + (win&7)*4 + (win>>3)]  (nf-permuted fragment layout)
__device__ __align__(16) uint32_t g_Hp[BB * KPP * WPAD];
__device__ float g_cwT[CC * 3 * EMB];   // [c][j][e]

// ===========================================================================
// Kernel 0: transpose conv_w [c][e][j] -> [c][j][e]
// ===========================================================================
__global__ void prep_cw(const float* __restrict__ conv_w) {
    int i = blockIdx.x * 256 + threadIdx.x;
    if (i < CC * EMB * 3) {
        int c = i / (EMB * 3);
        int r = i - c * (EMB * 3);
        int e = r / 3, j = r - e * 3;
        g_cwT[(c * 3 + j) * EMB + e] = conv_w[i];
    }
}

// ===========================================================================
// Kernel 1: embedding + conv1d(k=3,same) + tanh -> permuted half2 g_Hp
// ===========================================================================
#define CT_W    40
#define CT_ROWS (CT_W + 2)

__device__ __forceinline__ float dot4(float4 a, float4 b, float acc) {
    return fmaf(a.x, b.x, fmaf(a.y, b.y, fmaf(a.z, b.z, fmaf(a.w, b.w, acc))));
}
__device__ __forceinline__ float tanh_fast(float x) {
    float y;
    asm("tanh.approx.f32 %0, %1;" : "=f"(y) : "f"(x));
    return y;
}

__global__ __launch_bounds__(256)
void conv_kernel(const int* __restrict__ x, const float* __restrict__ W_embed,
                 const float* __restrict__ conv_b) {
    __shared__ __align__(16) float emb_s[CT_ROWS][104];
    __shared__ int tok_s[CT_ROWS];
    const int b  = blockIdx.y;
    const int w0 = blockIdx.x * CT_W;
    const int tid = threadIdx.x;

    if (tid < CT_ROWS) {
        int w = w0 - 1 + tid;
        tok_s[tid] = (w >= 0 && w < WLEN) ? x[b * WLEN + w] : -1;
    }
    __syncthreads();
    for (int i = tid; i < CT_ROWS * 25; i += 256) {
        int r = i / 25, q = i - r * 25;
        int t = tok_s[r];
        float4 v = make_float4(0.f, 0.f, 0.f, 0.f);
        if (t >= 0) v = *(const float4*)&W_embed[(long)t * EMB + q * 4];
        *(float4*)&emb_s[r][q * 4] = v;
    }
    __syncthreads();

    if (tid < 250) {
        const int p = tid / 10, q = tid - p * 10;
        const int wl = q * 4;
        float acc[2][4];
        float b0 = conv_b[2 * p], b1 = conv_b[2 * p + 1];
#pragma unroll
        for (int w = 0; w < 4; w++) { acc[0][w] = b0; acc[1][w] = b1; }

        const float* cw0 = &g_cwT[(2 * p) * 3 * EMB];
        const float* cw1 = &g_cwT[(2 * p + 1) * 3 * EMB];

        for (int e4 = 0; e4 < 25; e4++) {
            float4 v[6];
#pragma unroll
            for (int r = 0; r < 6; r++) v[r] = *(const float4*)&emb_s[wl + r][e4 * 4];
            float4 c00 = *(const float4*)(cw0 + e4 * 4);
            float4 c01 = *(const float4*)(cw0 + EMB + e4 * 4);
            float4 c02 = *(const float4*)(cw0 + 2 * EMB + e4 * 4);
            float4 c10 = *(const float4*)(cw1 + e4 * 4);
            float4 c11 = *(const float4*)(cw1 + EMB + e4 * 4);
            float4 c12 = *(const float4*)(cw1 + 2 * EMB + e4 * 4);
#pragma unroll
            for (int w = 0; w < 4; w++) {
                acc[0][w] = dot4(v[w], c00, acc[0][w]);
                acc[0][w] = dot4(v[w + 1], c01, acc[0][w]);
                acc[0][w] = dot4(v[w + 2], c02, acc[0][w]);
                acc[1][w] = dot4(v[w], c10, acc[1][w]);
                acc[1][w] = dot4(v[w + 1], c11, acc[1][w]);
                acc[1][w] = dot4(v[w + 2], c12, acc[1][w]);
            }
        }
#pragma unroll
        for (int i = 0; i < 4; i++) {
            __half2 h = __floats2half2_rn(tanh_fast(acc[0][i]), tanh_fast(acc[1][i]));
            int w = w0 + wl + i;
            int ch = w >> 5, win = w & 31;
            g_Hp[((b * KPP + p) << 10) + (ch << 5) + ((win & 7) << 2) + (win >> 3)]
                = *(uint32_t*)&h;
        }
    }
}

// ===========================================================================
// Kernel 2: dual GEMM, mma.sync fp16 (3x k16 + 1x k8 = K56), NO smem/barriers.
//   Warp = m16 labels x n32 w; B fragments via coalesced LDG.128 from the
//   permuted gmem layout. Fused exp2-softmax-pool epilogue.
// ===========================================================================
#define NCH 32

#define MMA_F16(C, A0, A1, A2, A3, B0, B1)                                  \
    asm volatile(                                                           \
        "mma.sync.aligned.m16n8k16.row.col.f32.f16.f16.f32 "                \
        "{%0,%1,%2,%3}, {%4,%5,%6,%7}, {%8,%9}, {%0,%1,%2,%3};"             \
        : "+f"((C)[0]), "+f"((C)[1]), "+f"((C)[2]), "+f"((C)[3])            \
        : "r"(A0), "r"(A1), "r"(A2), "r"(A3), "r"(B0), "r"(B1))

#define MMA_F16K8(C, A0, A1, B0)                                            \
    asm volatile(                                                           \
        "mma.sync.aligned.m16n8k8.row.col.f32.f16.f16.f32 "                 \
        "{%0,%1,%2,%3}, {%4,%5}, {%6}, {%0,%1,%2,%3};"                      \
        : "+f"((C)[0]), "+f"((C)[1]), "+f"((C)[2]), "+f"((C)[3])            \
        : "r"(A0), "r"(A1), "r"(B0))

__device__ __forceinline__ uint32_t packh2(float lo, float hi) {
    __half2 h = __floats2half2_rn(lo, hi);
    return *(uint32_t*)&h;
}
__device__ __forceinline__ float ex2f(float x) {
    float y;
    asm("ex2.approx.f32 %0, %1;" : "=f"(y) : "f"(x));
    return y;
}

__global__ __launch_bounds__(256)
void attn_kernel(const float* __restrict__ u_w, const float* __restrict__ out_w,
                 const float* __restrict__ out_b, float* __restrict__ out) {
    const int tid  = threadIdx.x;
    const int b    = blockIdx.y;
    const int l0   = blockIdx.x * 128;
    const int lane = tid & 31;
    const int wid  = tid >> 5;
    const int gid  = lane >> 2;
    const int tig  = lane & 3;

    // ---- Hoisted A fragments: U pre-scaled by log2(e); k-pairs kp = base+tig
    const float LOG2E = 1.4426950408889634f;
    uint32_t uA[3][4], oA[3][4], uA3[2], oA3[2];
#pragma unroll
    for (int ks = 0; ks < 3; ks++)
#pragma unroll
        for (int h = 0; h < 2; h++) {
            int kp = ks * 8 + tig + h * 4;
#pragma unroll
            for (int mo = 0; mo < 2; mo++) {
                int l = l0 + wid * 16 + gid + mo * 8;
                float2 uv = make_float2(0.f, 0.f), ov = make_float2(0.f, 0.f);
                if (l < LL) {
                    uv = *(const float2*)&u_w[l * CC + 2 * kp];
                    ov = *(const float2*)&out_w[l * CC + 2 * kp];
                }
                uA[ks][h * 2 + mo] = packh2(uv.x * LOG2E, uv.y * LOG2E);
                oA[ks][h * 2 + mo] = packh2(ov.x, ov.y);
            }
        }
    {
        int kp = 24 + tig;   // k 48..55; k>=50 zero-padded below
#pragma unroll
        for (int mo = 0; mo < 2; mo++) {
            int l = l0 + wid * 16 + gid + mo * 8;
            float u0 = 0.f, u1 = 0.f, o0 = 0.f, o1 = 0.f;
            if (l < LL) {
                u0 = u_w[l * CC + 2 * kp];
                o0 = out_w[l * CC + 2 * kp];
                if (2 * kp + 1 < CC) {
                    u1 = u_w[l * CC + 2 * kp + 1];
                    o1 = out_w[l * CC + 2 * kp + 1];
                }
            }
            uA3[mo] = packh2(u0 * LOG2E, u1 * LOG2E);
            oA3[mo] = packh2(o0, o1);
        }
    }

    // B base: row (kp = tig), rows advance by 4 per fragment pair slot
    const uint32_t* Hb = g_Hp + (b * KPP + tig) * WPAD;

    float dacc[2] = {0.f, 0.f}, nacc[2] = {0.f, 0.f};

    for (int ch = 0; ch < NCH - 1; ch++) {
        const int cw = ch * 32 + gid * 4;
        uint4 f[7];
#pragma unroll
        for (int j = 0; j < 7; j++)
            f[j] = *(const uint4*)(Hb + j * 4 * WPAD + cw);

        float sacc[4][4], pacc[4][4];
#pragma unroll
        for (int nf = 0; nf < 4; nf++)
#pragma unroll
            for (int c = 0; c < 4; c++) { sacc[nf][c] = 0.f; pacc[nf][c] = 0.f; }

        const uint32_t* fw = (const uint32_t*)f;
#pragma unroll
        for (int ks = 0; ks < 3; ks++) {
#pragma unroll
            for (int nf = 0; nf < 4; nf++) {
                uint32_t b0 = fw[(2 * ks) * 4 + nf];
                uint32_t b1 = fw[(2 * ks + 1) * 4 + nf];
                MMA_F16(sacc[nf], uA[ks][0], uA[ks][1], uA[ks][2], uA[ks][3], b0, b1);
                MMA_F16(pacc[nf], oA[ks][0], oA[ks][1], oA[ks][2], oA[ks][3], b0, b1);
            }
        }
#pragma unroll
        for (int nf = 0; nf < 4; nf++) {
            uint32_t b0 = fw[6 * 4 + nf];
            MMA_F16K8(sacc[nf], uA3[0], uA3[1], b0);
            MMA_F16K8(pacc[nf], oA3[0], oA3[1], b0);
        }

#pragma unroll
        for (int nf = 0; nf < 4; nf++)
#pragma unroll
            for (int c = 0; c < 4; c++) {
                float e = ex2f(sacc[nf][c]);
                int r = c >> 1;
                dacc[r] += e;
                nacc[r] = fmaf(e, pacc[nf][c], nacc[r]);
            }
    }

    // ---- Tail chunk (ch=31): valid w = 992..999 -> nf == 0 only
    {
        const int cw = 31 * 32 + gid * 4;
        uint32_t t[7];
#pragma unroll
        for (int j = 0; j < 7; j++)
            t[j] = Hb[j * 4 * WPAD + cw];   // word nf=0

        float s4[4] = {0.f, 0.f, 0.f, 0.f}, p4[4] = {0.f, 0.f, 0.f, 0.f};
#pragma unroll
        for (int ks = 0; ks < 3; ks++) {
            MMA_F16(s4, uA[ks][0], uA[ks][1], uA[ks][2], uA[ks][3], t[2 * ks], t[2 * ks + 1]);
            MMA_F16(p4, oA[ks][0], oA[ks][1], oA[ks][2], oA[ks][3], t[2 * ks], t[2 * ks + 1]);
        }
        MMA_F16K8(s4, uA3[0], uA3[1], t[6]);
        MMA_F16K8(p4, oA3[0], oA3[1], t[6]);
#pragma unroll
        for (int c = 0; c < 4; c++) {
            float e = ex2f(s4[c]);
            int r = c >> 1;
            dacc[r] += e;
            nacc[r] = fmaf(e, p4[c], nacc[r]);
        }
    }

    // ---- Reduce over 4 k-group lanes (different w), then sigmoid + store
#pragma unroll
    for (int r = 0; r < 2; r++) {
        dacc[r] += __shfl_xor_sync(0xffffffffu, dacc[r], 1);
        dacc[r] += __shfl_xor_sync(0xffffffffu, dacc[r], 2);
        nacc[r] += __shfl_xor_sync(0xffffffffu, nacc[r], 1);
        nacc[r] += __shfl_xor_sync(0xffffffffu, nacc[r], 2);
    }
    if (tig == 0) {
#pragma unroll
        for (int r = 0; r < 2; r++) {
            int l = l0 + wid * 16 + gid + r * 8;
            if (l < LL) {
                float z = nacc[r] / dacc[r] + out_b[l];
                out[b * LL + l] = 1.f / (1.f + __expf(-z));
            }
        }
    }
}

// ===========================================================================
extern "C" void kernel_launch(void* const* d_in, const int* in_sizes, int n_in,
                              void* d_out, int out_size) {
    const int*   x       = (const int*)  d_in[0];
    const float* W_embed = (const float*)d_in[1];
    const float* conv_w  = (const float*)d_in[2];
    const float* conv_b  = (const float*)d_in[3];
    const float* u_w     = (const float*)d_in[4];
    const float* out_w   = (const float*)d_in[5];
    const float* out_b   = (const float*)d_in[6];
    float* out = (float*)d_out;

    prep_cw<<<(CC * EMB * 3 + 255) / 256, 256>>>(conv_w);

    dim3 cgrid(WLEN / CT_W, BB);          // (25, 8)
    conv_kernel<<<cgrid, 256>>>(x, W_embed, conv_b);

    dim3 agrid((LL + 127) / 128, BB);     // (141, 8)
    attn_kernel<<<agrid, 256>>>(u_w, out_w, out_b, out);
}

// round 7
// speedup vs baseline: 1.0492x; 1.0492x over previous
#include <cuda_runtime.h>
#include <cuda_fp16.h>
#include <math.h>
#include <stdint.h>

#define BB   8
#define WLEN 1000
#define EMB  100
#define CC   50
#define LL   18000

#define KPP  32      // padded k-pair rows (k padded 50 -> 64; only 0..24 written)
#define WPAD 1024    // padded w words per row (32 chunks x 32)

// zero-initialized device globals; padding rows/words stay zero forever.
// layout: [b][kp][ch*32 + (win&7)*4 + (win>>3)]  (nf-permuted fragment layout)
__device__ __align__(16) uint32_t g_Hp[BB * KPP * WPAD];
__device__ float g_cwT[CC * 3 * EMB];   // [c][j][e]

// ===========================================================================
// Kernel 0: transpose conv_w [c][e][j] -> [c][j][e]
// ===========================================================================
__global__ void prep_cw(const float* __restrict__ conv_w) {
    int i = blockIdx.x * 256 + threadIdx.x;
    if (i < CC * EMB * 3) {
        int c = i / (EMB * 3);
        int r = i - c * (EMB * 3);
        int e = r / 3, j = r - e * 3;
        g_cwT[(c * 3 + j) * EMB + e] = conv_w[i];
    }
}

// ===========================================================================
// Kernel 1: embedding + conv1d(k=3,same) + tanh -> permuted half2 g_Hp
// ===========================================================================
#define CT_W    40
#define CT_ROWS (CT_W + 2)

__device__ __forceinline__ float dot4(float4 a, float4 b, float acc) {
    return fmaf(a.x, b.x, fmaf(a.y, b.y, fmaf(a.z, b.z, fmaf(a.w, b.w, acc))));
}
__device__ __forceinline__ float tanh_fast(float x) {
    float y;
    asm("tanh.approx.f32 %0, %1;" : "=f"(y) : "f"(x));
    return y;
}

__global__ __launch_bounds__(256)
void conv_kernel(const int* __restrict__ x, const float* __restrict__ W_embed,
                 const float* __restrict__ conv_b) {
    __shared__ __align__(16) float emb_s[CT_ROWS][104];
    __shared__ int tok_s[CT_ROWS];
    const int b  = blockIdx.y;
    const int w0 = blockIdx.x * CT_W;
    const int tid = threadIdx.x;

    if (tid < CT_ROWS) {
        int w = w0 - 1 + tid;
        tok_s[tid] = (w >= 0 && w < WLEN) ? x[b * WLEN + w] : -1;
    }
    __syncthreads();
    for (int i = tid; i < CT_ROWS * 25; i += 256) {
        int r = i / 25, q = i - r * 25;
        int t = tok_s[r];
        float4 v = make_float4(0.f, 0.f, 0.f, 0.f);
        if (t >= 0) v = *(const float4*)&W_embed[(long)t * EMB + q * 4];
        *(float4*)&emb_s[r][q * 4] = v;
    }
    __syncthreads();

    if (tid < 250) {
        const int p = tid / 10, q = tid - p * 10;
        const int wl = q * 4;
        float acc[2][4];
        float b0 = conv_b[2 * p], b1 = conv_b[2 * p + 1];
#pragma unroll
        for (int w = 0; w < 4; w++) { acc[0][w] = b0; acc[1][w] = b1; }

        const float* cw0 = &g_cwT[(2 * p) * 3 * EMB];
        const float* cw1 = &g_cwT[(2 * p + 1) * 3 * EMB];

        for (int e4 = 0; e4 < 25; e4++) {
            float4 v[6];
#pragma unroll
            for (int r = 0; r < 6; r++) v[r] = *(const float4*)&emb_s[wl + r][e4 * 4];
            float4 c00 = *(const float4*)(cw0 + e4 * 4);
            float4 c01 = *(const float4*)(cw0 + EMB + e4 * 4);
            float4 c02 = *(const float4*)(cw0 + 2 * EMB + e4 * 4);
            float4 c10 = *(const float4*)(cw1 + e4 * 4);
            float4 c11 = *(const float4*)(cw1 + EMB + e4 * 4);
            float4 c12 = *(const float4*)(cw1 + 2 * EMB + e4 * 4);
#pragma unroll
            for (int w = 0; w < 4; w++) {
                acc[0][w] = dot4(v[w], c00, acc[0][w]);
                acc[0][w] = dot4(v[w + 1], c01, acc[0][w]);
                acc[0][w] = dot4(v[w + 2], c02, acc[0][w]);
                acc[1][w] = dot4(v[w], c10, acc[1][w]);
                acc[1][w] = dot4(v[w + 1], c11, acc[1][w]);
                acc[1][w] = dot4(v[w + 2], c12, acc[1][w]);
            }
        }
#pragma unroll
        for (int i = 0; i < 4; i++) {
            __half2 h = __floats2half2_rn(tanh_fast(acc[0][i]), tanh_fast(acc[1][i]));
            int w = w0 + wl + i;
            int ch = w >> 5, win = w & 31;
            g_Hp[((b * KPP + p) << 10) + (ch << 5) + ((win & 7) << 2) + (win >> 3)]
                = *(uint32_t*)&h;
        }
    }
}

// ===========================================================================
// Kernel 2: dual GEMM, mma.sync fp16 (3x k16 + 1x k8 = K56), no smem/barriers,
//   register-double-buffered B fragments (prefetch chunk n+1 during chunk n).
// ===========================================================================
#define MMA_F16(C, A0, A1, A2, A3, B0, B1)                                  \
    asm volatile(                                                           \
        "mma.sync.aligned.m16n8k16.row.col.f32.f16.f16.f32 "                \
        "{%0,%1,%2,%3}, {%4,%5,%6,%7}, {%8,%9}, {%0,%1,%2,%3};"             \
        : "+f"((C)[0]), "+f"((C)[1]), "+f"((C)[2]), "+f"((C)[3])            \
        : "r"(A0), "r"(A1), "r"(A2), "r"(A3), "r"(B0), "r"(B1))

#define MMA_F16K8(C, A0, A1, B0)                                            \
    asm volatile(                                                           \
        "mma.sync.aligned.m16n8k8.row.col.f32.f16.f16.f32 "                 \
        "{%0,%1,%2,%3}, {%4,%5}, {%6}, {%0,%1,%2,%3};"                      \
        : "+f"((C)[0]), "+f"((C)[1]), "+f"((C)[2]), "+f"((C)[3])            \
        : "r"(A0), "r"(A1), "r"(B0))

__device__ __forceinline__ uint32_t packh2(float lo, float hi) {
    __half2 h = __floats2half2_rn(lo, hi);
    return *(uint32_t*)&h;
}
__device__ __forceinline__ float ex2f(float x) {
    float y;
    asm("ex2.approx.f32 %0, %1;" : "=f"(y) : "f"(x));
    return y;
}

struct AF { uint32_t uA[3][4], oA[3][4], uA3[2], oA3[2]; };

__device__ __forceinline__ void load_chunk(uint4 f[7], const uint32_t* Hbg, int ch) {
#pragma unroll
    for (int j = 0; j < 7; j++)
        f[j] = *(const uint4*)(Hbg + j * 4 * WPAD + ch * 32);
}

__device__ __forceinline__ void compute_chunk(const uint4 f[7], const AF& A,
                                              float dacc[2], float nacc[2]) {
    float sacc[4][4], pacc[4][4];
#pragma unroll
    for (int nf = 0; nf < 4; nf++)
#pragma unroll
        for (int c = 0; c < 4; c++) { sacc[nf][c] = 0.f; pacc[nf][c] = 0.f; }

    const uint32_t* fw = (const uint32_t*)f;
#pragma unroll
    for (int ks = 0; ks < 3; ks++) {
#pragma unroll
        for (int nf = 0; nf < 4; nf++) {
            uint32_t b0 = fw[(2 * ks) * 4 + nf];
            uint32_t b1 = fw[(2 * ks + 1) * 4 + nf];
            MMA_F16(sacc[nf], A.uA[ks][0], A.uA[ks][1], A.uA[ks][2], A.uA[ks][3], b0, b1);
            MMA_F16(pacc[nf], A.oA[ks][0], A.oA[ks][1], A.oA[ks][2], A.oA[ks][3], b0, b1);
        }
    }
#pragma unroll
    for (int nf = 0; nf < 4; nf++) {
        uint32_t b0 = fw[6 * 4 + nf];
        MMA_F16K8(sacc[nf], A.uA3[0], A.uA3[1], b0);
        MMA_F16K8(pacc[nf], A.oA3[0], A.oA3[1], b0);
    }
#pragma unroll
    for (int nf = 0; nf < 4; nf++)
#pragma unroll
        for (int c = 0; c < 4; c++) {
            float e = ex2f(sacc[nf][c]);
            int r = c >> 1;
            dacc[r] += e;
            nacc[r] = fmaf(e, pacc[nf][c], nacc[r]);
        }
}

__global__ __launch_bounds__(256)
void attn_kernel(const float* __restrict__ u_w, const float* __restrict__ out_w,
                 const float* __restrict__ out_b, float* __restrict__ out) {
    const int tid  = threadIdx.x;
    const int b    = blockIdx.y;
    const int l0   = blockIdx.x * 128;
    const int lane = tid & 31;
    const int wid  = tid >> 5;
    const int gid  = lane >> 2;
    const int tig  = lane & 3;

    // ---- Hoisted A fragments: U pre-scaled by log2(e)
    const float LOG2E = 1.4426950408889634f;
    AF A;
#pragma unroll
    for (int ks = 0; ks < 3; ks++)
#pragma unroll
        for (int h = 0; h < 2; h++) {
            int kp = ks * 8 + tig + h * 4;
#pragma unroll
            for (int mo = 0; mo < 2; mo++) {
                int l = l0 + wid * 16 + gid + mo * 8;
                float2 uv = make_float2(0.f, 0.f), ov = make_float2(0.f, 0.f);
                if (l < LL) {
                    uv = *(const float2*)&u_w[l * CC + 2 * kp];
                    ov = *(const float2*)&out_w[l * CC + 2 * kp];
                }
                A.uA[ks][h * 2 + mo] = packh2(uv.x * LOG2E, uv.y * LOG2E);
                A.oA[ks][h * 2 + mo] = packh2(ov.x, ov.y);
            }
        }
    {
        int kp = 24 + tig;   // k 48..55; k>=50 zeroed
#pragma unroll
        for (int mo = 0; mo < 2; mo++) {
            int l = l0 + wid * 16 + gid + mo * 8;
            float u0 = 0.f, u1 = 0.f, o0 = 0.f, o1 = 0.f;
            if (l < LL) {
                u0 = u_w[l * CC + 2 * kp];
                o0 = out_w[l * CC + 2 * kp];
                if (2 * kp + 1 < CC) {
                    u1 = u_w[l * CC + 2 * kp + 1];
                    o1 = out_w[l * CC + 2 * kp + 1];
                }
            }
            A.uA3[mo] = packh2(u0 * LOG2E, u1 * LOG2E);
            A.oA3[mo] = packh2(o0, o1);
        }
    }

    const uint32_t* Hbg = g_Hp + (b * KPP + tig) * WPAD + gid * 4;

    float dacc[2] = {0.f, 0.f}, nacc[2] = {0.f, 0.f};

    // ---- Software-pipelined main loop over 31 full chunks (0..30)
    uint4 fa[7], fb[7];
    load_chunk(fa, Hbg, 0);
#pragma unroll 1
    for (int ch = 0; ch < 30; ch += 2) {
        load_chunk(fb, Hbg, ch + 1);
        compute_chunk(fa, A, dacc, nacc);
        load_chunk(fa, Hbg, ch + 2);
        compute_chunk(fb, A, dacc, nacc);
    }
    // prefetch tail words (w 992..999 -> nf==0 word only), compute chunk 30
    uint32_t t[7];
#pragma unroll
    for (int j = 0; j < 7; j++)
        t[j] = Hbg[j * 4 * WPAD + 31 * 32];
    compute_chunk(fa, A, dacc, nacc);

    // ---- Tail chunk (ch=31): nf == 0 only
    {
        float s4[4] = {0.f, 0.f, 0.f, 0.f}, p4[4] = {0.f, 0.f, 0.f, 0.f};
#pragma unroll
        for (int ks = 0; ks < 3; ks++) {
            MMA_F16(s4, A.uA[ks][0], A.uA[ks][1], A.uA[ks][2], A.uA[ks][3],
                    t[2 * ks], t[2 * ks + 1]);
            MMA_F16(p4, A.oA[ks][0], A.oA[ks][1], A.oA[ks][2], A.oA[ks][3],
                    t[2 * ks], t[2 * ks + 1]);
        }
        MMA_F16K8(s4, A.uA3[0], A.uA3[1], t[6]);
        MMA_F16K8(p4, A.oA3[0], A.oA3[1], t[6]);
#pragma unroll
        for (int c = 0; c < 4; c++) {
            float e = ex2f(s4[c]);
            int r = c >> 1;
            dacc[r] += e;
            nacc[r] = fmaf(e, p4[c], nacc[r]);
        }
    }

    // ---- Reduce over 4 k-group lanes (different w), sigmoid, store
#pragma unroll
    for (int r = 0; r < 2; r++) {
        dacc[r] += __shfl_xor_sync(0xffffffffu, dacc[r], 1);
        dacc[r] += __shfl_xor_sync(0xffffffffu, dacc[r], 2);
        nacc[r] += __shfl_xor_sync(0xffffffffu, nacc[r], 1);
        nacc[r] += __shfl_xor_sync(0xffffffffu, nacc[r], 2);
    }
    if (tig == 0) {
#pragma unroll
        for (int r = 0; r < 2; r++) {
            int l = l0 + wid * 16 + gid + r * 8;
            if (l < LL) {
                float z = nacc[r] / dacc[r] + out_b[l];
                out[b * LL + l] = 1.f / (1.f + __expf(-z));
            }
        }
    }
}

// ===========================================================================
extern "C" void kernel_launch(void* const* d_in, const int* in_sizes, int n_in,
                              void* d_out, int out_size) {
    const int*   x       = (const int*)  d_in[0];
    const float* W_embed = (const float*)d_in[1];
    const float* conv_w  = (const float*)d_in[2];
    const float* conv_b  = (const float*)d_in[3];
    const float* u_w     = (const float*)d_in[4];
    const float* out_w   = (const float*)d_in[5];
    const float* out_b   = (const float*)d_in[6];
    float* out = (float*)d_out;

    prep_cw<<<(CC * EMB * 3 + 255) / 256, 256>>>(conv_w);

    dim3 cgrid(WLEN / CT_W, BB);          // (25, 8)
    conv_kernel<<<cgrid, 256>>>(x, W_embed, conv_b);

    dim3 agrid((LL + 127) / 128, BB);     // (141, 8)
    attn_kernel<<<agrid, 256>>>(u_w, out_w, out_b, out);
}

// round 8
// speedup vs baseline: 1.2332x; 1.1753x over previous
#include <cuda_runtime.h>
#include <cuda_fp16.h>
#include <math.h>
#include <stdint.h>

#define BB   8
#define WLEN 1000
#define EMB  100
#define CC   50
#define LL   18000

#define WPAD 1024
// H: [b][w][k-halves], 64 halves (128B) per w row; k>=50 and w>=1000 stay zero
__device__ __align__(16) uint32_t g_Hh[BB * WPAD * 32];

// ===========================================================================
// Kernel 1: embedding + conv1d(k=3,same) + tanh -> g_Hh[b][w][k]
// ===========================================================================
#define CT_W    40
#define CT_ROWS (CT_W + 2)

__device__ __forceinline__ float tanh_fast(float x) {
    float y;
    asm("tanh.approx.f32 %0, %1;" : "=f"(y) : "f"(x));
    return y;
}

__global__ __launch_bounds__(256)
void conv_kernel(const int* __restrict__ x, const float* __restrict__ W_embed,
                 const float* __restrict__ conv_w, const float* __restrict__ conv_b) {
    __shared__ __align__(16) float emb_s[CT_ROWS][104];
    __shared__ int tok_s[CT_ROWS];
    const int b  = blockIdx.y;
    const int w0 = blockIdx.x * CT_W;
    const int tid = threadIdx.x;

    if (tid < CT_ROWS) {
        int w = w0 - 1 + tid;
        tok_s[tid] = (w >= 0 && w < WLEN) ? x[b * WLEN + w] : -1;
    }
    __syncthreads();
    for (int i = tid; i < CT_ROWS * 25; i += 256) {
        int r = i / 25, q = i - r * 25;
        int t = tok_s[r];
        float4 v = make_float4(0.f, 0.f, 0.f, 0.f);
        if (t >= 0) v = *(const float4*)&W_embed[(long)t * EMB + q * 4];
        *(float4*)&emb_s[r][q * 4] = v;
    }
    __syncthreads();

    if (tid < 250) {
        const int p = tid / 10, q = tid - p * 10;   // p: channel pair, q: w group
        const int wl = q * 4;
        const int c0 = 2 * p, c1 = 2 * p + 1;
        float acc[2][4];
        float bias0 = conv_b[c0], bias1 = conv_b[c1];
#pragma unroll
        for (int w = 0; w < 4; w++) { acc[0][w] = bias0; acc[1][w] = bias1; }

        const float4* cw0 = (const float4*)(conv_w + c0 * EMB * 3);
        const float4* cw1 = (const float4*)(conv_w + c1 * EMB * 3);

        for (int e4 = 0; e4 < 25; e4++) {
            float4 v[6];
#pragma unroll
            for (int r = 0; r < 6; r++) v[r] = *(const float4*)&emb_s[wl + r][e4 * 4];

            // 12 consecutive floats per channel = taps for e4*4 .. e4*4+3
            float4 q0 = cw0[e4 * 3], q1 = cw0[e4 * 3 + 1], q2 = cw0[e4 * 3 + 2];
#pragma unroll
            for (int w = 0; w < 4; w++) {
                acc[0][w] = fmaf(v[w].x, q0.x, acc[0][w]);
                acc[0][w] = fmaf(v[w + 1].x, q0.y, acc[0][w]);
                acc[0][w] = fmaf(v[w + 2].x, q0.z, acc[0][w]);
                acc[0][w] = fmaf(v[w].y, q0.w, acc[0][w]);
                acc[0][w] = fmaf(v[w + 1].y, q1.x, acc[0][w]);
                acc[0][w] = fmaf(v[w + 2].y, q1.y, acc[0][w]);
                acc[0][w] = fmaf(v[w].z, q1.z, acc[0][w]);
                acc[0][w] = fmaf(v[w + 1].z, q1.w, acc[0][w]);
                acc[0][w] = fmaf(v[w + 2].z, q2.x, acc[0][w]);
                acc[0][w] = fmaf(v[w].w, q2.y, acc[0][w]);
                acc[0][w] = fmaf(v[w + 1].w, q2.z, acc[0][w]);
                acc[0][w] = fmaf(v[w + 2].w, q2.w, acc[0][w]);
            }
            q0 = cw1[e4 * 3]; q1 = cw1[e4 * 3 + 1]; q2 = cw1[e4 * 3 + 2];
#pragma unroll
            for (int w = 0; w < 4; w++) {
                acc[1][w] = fmaf(v[w].x, q0.x, acc[1][w]);
                acc[1][w] = fmaf(v[w + 1].x, q0.y, acc[1][w]);
                acc[1][w] = fmaf(v[w + 2].x, q0.z, acc[1][w]);
                acc[1][w] = fmaf(v[w].y, q0.w, acc[1][w]);
                acc[1][w] = fmaf(v[w + 1].y, q1.x, acc[1][w]);
                acc[1][w] = fmaf(v[w + 2].y, q1.y, acc[1][w]);
                acc[1][w] = fmaf(v[w].z, q1.z, acc[1][w]);
                acc[1][w] = fmaf(v[w + 1].z, q1.w, acc[1][w]);
                acc[1][w] = fmaf(v[w + 2].z, q2.x, acc[1][w]);
                acc[1][w] = fmaf(v[w].w, q2.y, acc[1][w]);
                acc[1][w] = fmaf(v[w + 1].w, q2.z, acc[1][w]);
                acc[1][w] = fmaf(v[w + 2].w, q2.w, acc[1][w]);
            }
        }
#pragma unroll
        for (int i = 0; i < 4; i++) {
            __half2 h = __floats2half2_rn(tanh_fast(acc[0][i]), tanh_fast(acc[1][i]));
            g_Hh[((b * WPAD) + w0 + wl + i) * 32 + p] = *(uint32_t*)&h;
        }
    }
}

// ===========================================================================
// Kernel 2: dual GEMM mma.sync fp16 (3x k16 + 1x k8 = K56), smem double-buffer
//   with ldmatrix.x4 B-fragment loads (7 LDSM/chunk vs 32 LDS).
//   Warp = m16 labels x n32 w; smem chunk layout: 32 w-rows x 72 halves.
// ===========================================================================
#define ROWH 72                    // halves per smem row (144B: conflict-free)
#define ROWB 144

#define MMA_F16(C, A0, A1, A2, A3, B0, B1)                                  \
    asm volatile(                                                           \
        "mma.sync.aligned.m16n8k16.row.col.f32.f16.f16.f32 "                \
        "{%0,%1,%2,%3}, {%4,%5,%6,%7}, {%8,%9}, {%0,%1,%2,%3};"             \
        : "+f"((C)[0]), "+f"((C)[1]), "+f"((C)[2]), "+f"((C)[3])            \
        : "r"(A0), "r"(A1), "r"(A2), "r"(A3), "r"(B0), "r"(B1))

#define MMA_F16K8(C, A0, A1, B0)                                            \
    asm volatile(                                                           \
        "mma.sync.aligned.m16n8k8.row.col.f32.f16.f16.f32 "                 \
        "{%0,%1,%2,%3}, {%4,%5}, {%6}, {%0,%1,%2,%3};"                      \
        : "+f"((C)[0]), "+f"((C)[1]), "+f"((C)[2]), "+f"((C)[3])            \
        : "r"(A0), "r"(A1), "r"(B0))

#define LDSM_X4(R, A)                                                       \
    asm volatile("ldmatrix.sync.aligned.m8n8.x4.shared.b16 "                \
                 "{%0,%1,%2,%3}, [%4];"                                     \
                 : "=r"((R)[0]), "=r"((R)[1]), "=r"((R)[2]), "=r"((R)[3])   \
                 : "r"(A))

#define LDSM_X1(R, A)                                                       \
    asm volatile("ldmatrix.sync.aligned.m8n8.x1.shared.b16 {%0}, [%1];"     \
                 : "=r"(R) : "r"(A))

__device__ __forceinline__ uint32_t packh2(float lo, float hi) {
    __half2 h = __floats2half2_rn(lo, hi);
    return *(uint32_t*)&h;
}
__device__ __forceinline__ float ex2f(float x) {
    float y;
    asm("ex2.approx.f32 %0, %1;" : "=f"(y) : "f"(x));
    return y;
}
__device__ __forceinline__ uint32_t cvta_smem(const void* p) {
    uint32_t a;
    asm("{ .reg .u64 t; cvta.to.shared.u64 t, %1; cvt.u32.u64 %0, t; }"
        : "=r"(a) : "l"(p));
    return a;
}

__global__ __launch_bounds__(256, 2)
void attn_kernel(const float* __restrict__ u_w, const float* __restrict__ out_w,
                 const float* __restrict__ out_b, float* __restrict__ out) {
    __shared__ __align__(16) uint32_t Hs[2][32 * ROWH / 2];   // 2 x 4608B

    const int tid  = threadIdx.x;
    const int b    = blockIdx.y;
    const int l0   = blockIdx.x * 128;
    const int lane = tid & 31;
    const int wid  = tid >> 5;
    const int gid  = lane >> 2;
    const int tig  = lane & 3;

    // ---- Hoisted A fragments: U pre-scaled by log2(e); K56
    const float LOG2E = 1.4426950408889634f;
    uint32_t uA[3][4], oA[3][4], uA3[2], oA3[2];
#pragma unroll
    for (int ks = 0; ks < 3; ks++)
#pragma unroll
        for (int h = 0; h < 2; h++) {
            int kp = ks * 8 + tig + h * 4;
#pragma unroll
            for (int mo = 0; mo < 2; mo++) {
                int l = l0 + wid * 16 + gid + mo * 8;
                float2 uv = make_float2(0.f, 0.f), ov = make_float2(0.f, 0.f);
                if (l < LL) {
                    uv = *(const float2*)&u_w[l * CC + 2 * kp];
                    ov = *(const float2*)&out_w[l * CC + 2 * kp];
                }
                uA[ks][h * 2 + mo] = packh2(uv.x * LOG2E, uv.y * LOG2E);
                oA[ks][h * 2 + mo] = packh2(ov.x, ov.y);
            }
        }
    {
        int kp = 24 + tig;   // k 48..55; k>=50 zeroed
#pragma unroll
        for (int mo = 0; mo < 2; mo++) {
            int l = l0 + wid * 16 + gid + mo * 8;
            float u0 = 0.f, u1 = 0.f, o0 = 0.f, o1 = 0.f;
            if (l < LL && kp == 24) {   // only kp 24 (k48,49) is non-zero
                u0 = u_w[l * CC + 48]; u1 = u_w[l * CC + 49];
                o0 = out_w[l * CC + 48]; o1 = out_w[l * CC + 49];
            }
            uA3[mo] = packh2(u0 * LOG2E, u1 * LOG2E);
            oA3[mo] = packh2(o0, o1);
        }
    }

    // ---- loader indices: 256 threads x 1 uint4 = 32 rows x 128B
    const int lrow = tid >> 3, lseg = tid & 7;
    const uint32_t* gsrc = g_Hh + (b * WPAD + lrow) * 32 + lseg * 4;
    uint32_t s_base0 = cvta_smem(&Hs[0][0]);
    uint32_t s_base1 = cvta_smem(&Hs[1][0]);
    const uint32_t s_st = s_base0 + lrow * ROWB + lseg * 16;     // store addr buf0
    const uint32_t s_ld0 = s_base0 + lane * ROWB;                // ldmatrix base buf0
    const uint32_t s_ld1 = s_base1 + lane * ROWB;
    const uint32_t s_ldt0 = s_base0 + (lane & 7) * ROWB;         // x1 tail base
    const uint32_t s_ldt1 = s_base1 + (lane & 7) * ROWB;

    // prologue: chunk 0 -> buf0
    {
        uint4 v = *(const uint4*)gsrc;
        asm volatile("st.shared.v4.b32 [%0], {%1,%2,%3,%4};"
                     :: "r"(s_st), "r"(v.x), "r"(v.y), "r"(v.z), "r"(v.w));
    }
    __syncthreads();

    float dacc[2] = {0.f, 0.f}, nacc[2] = {0.f, 0.f};

#pragma unroll 1
    for (int ch = 0; ch < 31; ch++) {
        // prefetch chunk ch+1 into regs
        uint4 v = *(const uint4*)(gsrc + (ch + 1) * 32 * 32);

        const uint32_t sld = (ch & 1) ? s_ld1 : s_ld0;

        float sacc[4][4], pacc[4][4];
#pragma unroll
        for (int nf = 0; nf < 4; nf++)
#pragma unroll
            for (int c = 0; c < 4; c++) { sacc[nf][c] = 0.f; pacc[nf][c] = 0.f; }

#pragma unroll
        for (int ks = 0; ks < 3; ks++) {
            uint32_t b0v[4], b1v[4];
            LDSM_X4(b0v, sld + ks * 32);
            LDSM_X4(b1v, sld + ks * 32 + 16);
#pragma unroll
            for (int nf = 0; nf < 4; nf++) {
                MMA_F16(sacc[nf], uA[ks][0], uA[ks][1], uA[ks][2], uA[ks][3],
                        b0v[nf], b1v[nf]);
                MMA_F16(pacc[nf], oA[ks][0], oA[ks][1], oA[ks][2], oA[ks][3],
                        b0v[nf], b1v[nf]);
            }
        }
        {
            uint32_t bt[4];
            LDSM_X4(bt, sld + 96);
#pragma unroll
            for (int nf = 0; nf < 4; nf++) {
                MMA_F16K8(sacc[nf], uA3[0], uA3[1], bt[nf]);
                MMA_F16K8(pacc[nf], oA3[0], oA3[1], bt[nf]);
            }
        }

#pragma unroll
        for (int nf = 0; nf < 4; nf++)
#pragma unroll
            for (int c = 0; c < 4; c++) {
                float e = ex2f(sacc[nf][c]);
                int r = c >> 1;
                dacc[r] += e;
                nacc[r] = fmaf(e, pacc[nf][c], nacc[r]);
            }

        // write prefetched chunk into the other buffer
        uint32_t sst = ((ch & 1) ? s_base0 : s_base1) + lrow * ROWB + lseg * 16;
        asm volatile("st.shared.v4.b32 [%0], {%1,%2,%3,%4};"
                     :: "r"(sst), "r"(v.x), "r"(v.y), "r"(v.z), "r"(v.w));
        __syncthreads();
    }

    // ---- tail chunk 31 (in buf1): valid w = 992..999 -> nf==0 only
    {
        const uint32_t sld = s_ldt1;
        float s4[4] = {0.f, 0.f, 0.f, 0.f}, p4[4] = {0.f, 0.f, 0.f, 0.f};
#pragma unroll
        for (int ks = 0; ks < 3; ks++) {
            uint32_t b0, b1;
            LDSM_X1(b0, sld + ks * 32);
            LDSM_X1(b1, sld + ks * 32 + 16);
            MMA_F16(s4, uA[ks][0], uA[ks][1], uA[ks][2], uA[ks][3], b0, b1);
            MMA_F16(p4, oA[ks][0], oA[ks][1], oA[ks][2], oA[ks][3], b0, b1);
        }
        uint32_t bt;
        LDSM_X1(bt, sld + 96);
        MMA_F16K8(s4, uA3[0], uA3[1], bt);
        MMA_F16K8(p4, oA3[0], oA3[1], bt);
#pragma unroll
        for (int c = 0; c < 4; c++) {
            float e = ex2f(s4[c]);
            int r = c >> 1;
            dacc[r] += e;
            nacc[r] = fmaf(e, p4[c], nacc[r]);
        }
        (void)s_ldt0;
    }

    // ---- reduce over 4 k-group lanes (different w), sigmoid, store
#pragma unroll
    for (int r = 0; r < 2; r++) {
        dacc[r] += __shfl_xor_sync(0xffffffffu, dacc[r], 1);
        dacc[r] += __shfl_xor_sync(0xffffffffu, dacc[r], 2);
        nacc[r] += __shfl_xor_sync(0xffffffffu, nacc[r], 1);
        nacc[r] += __shfl_xor_sync(0xffffffffu, nacc[r], 2);
    }
    if (tig == 0) {
#pragma unroll
        for (int r = 0; r < 2; r++) {
            int l = l0 + wid * 16 + gid + r * 8;
            if (l < LL) {
                float z = nacc[r] / dacc[r] + out_b[l];
                out[b * LL + l] = 1.f / (1.f + __expf(-z));
            }
        }
    }
}

// ===========================================================================
extern "C" void kernel_launch(void* const* d_in, const int* in_sizes, int n_in,
                              void* d_out, int out_size) {
    const int*   x       = (const int*)  d_in[0];
    const float* W_embed = (const float*)d_in[1];
    const float* conv_w  = (const float*)d_in[2];
    const float* conv_b  = (const float*)d_in[3];
    const float* u_w     = (const float*)d_in[4];
    const float* out_w   = (const float*)d_in[5];
    const float* out_b   = (const float*)d_in[6];
    float* out = (float*)d_out;

    dim3 cgrid(WLEN / CT_W, BB);          // (25, 8)
    conv_kernel<<<cgrid, 256>>>(x, W_embed, conv_w, conv_b);

    dim3 agrid((LL + 127) / 128, BB);     // (141, 8)
    attn_kernel<<<agrid, 256>>>(u_w, out_w, out_b, out);
}

// round 9
// speedup vs baseline: 1.4985x; 1.2151x over previous
#include <cuda_runtime.h>
#include <cuda_fp16.h>
#include <math.h>
#include <stdint.h>

#define BB   8
#define WLEN 1000
#define EMB  100
#define CC   50
#define LL   18000

#define WPAD 1024
// H: [b][w][k-halves], 64 halves (128B) per w row; k>=50 and w>=1000 stay zero
__device__ __align__(16) uint32_t g_Hh[BB * WPAD * 32];

// ===========================================================================
// Kernel 1: embedding + conv1d(k=3,same) + tanh -> g_Hh[b][w][k]
// emb_s uses a swizzled layout: 16B-unit index = row*32 + (e4 ^ ((row>>2)&7))
// -> conflict-free LDS/STS (was ~10-way conflicted).
// ===========================================================================
#define CT_W    40
#define CT_ROWS (CT_W + 2)

__device__ __forceinline__ float tanh_fast(float x) {
    float y;
    asm("tanh.approx.f32 %0, %1;" : "=f"(y) : "f"(x));
    return y;
}

__global__ __launch_bounds__(256)
void conv_kernel(const int* __restrict__ x, const float* __restrict__ W_embed,
                 const float* __restrict__ conv_w, const float* __restrict__ conv_b) {
    __shared__ __align__(16) float emb_s[CT_ROWS * 128];   // 42 rows x 32 16B units
    __shared__ int tok_s[CT_ROWS];
    const int b  = blockIdx.y;
    const int w0 = blockIdx.x * CT_W;
    const int tid = threadIdx.x;

    if (tid < CT_ROWS) {
        int w = w0 - 1 + tid;
        tok_s[tid] = (w >= 0 && w < WLEN) ? x[b * WLEN + w] : -1;
    }
    __syncthreads();
    for (int i = tid; i < CT_ROWS * 25; i += 256) {
        int r = i / 25, g = i - r * 25;
        int t = tok_s[r];
        float4 v = make_float4(0.f, 0.f, 0.f, 0.f);
        if (t >= 0) v = *(const float4*)&W_embed[(long)t * EMB + g * 4];
        *(float4*)&emb_s[(r * 32 + (g ^ ((r >> 2) & 7))) * 4] = v;
    }
    __syncthreads();

    if (tid < 250) {
        const int p = tid / 10, q = tid - p * 10;   // p: channel pair, q: w group
        const int wl = q * 4;
        const int sw0 = q & 7, sw1 = (q + 1) & 7;
        const int c0 = 2 * p, c1 = 2 * p + 1;
        float acc[2][4];
        float bias0 = conv_b[c0], bias1 = conv_b[c1];
#pragma unroll
        for (int w = 0; w < 4; w++) { acc[0][w] = bias0; acc[1][w] = bias1; }

        const float4* cw0 = (const float4*)(conv_w + c0 * EMB * 3);
        const float4* cw1 = (const float4*)(conv_w + c1 * EMB * 3);

        for (int g = 0; g < 25; g++) {
            float4 v[6];
#pragma unroll
            for (int r = 0; r < 6; r++) {
                int sw = (r < 4) ? sw0 : sw1;
                v[r] = *(const float4*)&emb_s[((wl + r) * 32 + (g ^ sw)) * 4];
            }
            float4 q0 = cw0[g * 3], q1 = cw0[g * 3 + 1], q2 = cw0[g * 3 + 2];
#pragma unroll
            for (int w = 0; w < 4; w++) {
                acc[0][w] = fmaf(v[w].x, q0.x, acc[0][w]);
                acc[0][w] = fmaf(v[w + 1].x, q0.y, acc[0][w]);
                acc[0][w] = fmaf(v[w + 2].x, q0.z, acc[0][w]);
                acc[0][w] = fmaf(v[w].y, q0.w, acc[0][w]);
                acc[0][w] = fmaf(v[w + 1].y, q1.x, acc[0][w]);
                acc[0][w] = fmaf(v[w + 2].y, q1.y, acc[0][w]);
                acc[0][w] = fmaf(v[w].z, q1.z, acc[0][w]);
                acc[0][w] = fmaf(v[w + 1].z, q1.w, acc[0][w]);
                acc[0][w] = fmaf(v[w + 2].z, q2.x, acc[0][w]);
                acc[0][w] = fmaf(v[w].w, q2.y, acc[0][w]);
                acc[0][w] = fmaf(v[w + 1].w, q2.z, acc[0][w]);
                acc[0][w] = fmaf(v[w + 2].w, q2.w, acc[0][w]);
            }
            q0 = cw1[g * 3]; q1 = cw1[g * 3 + 1]; q2 = cw1[g * 3 + 2];
#pragma unroll
            for (int w = 0; w < 4; w++) {
                acc[1][w] = fmaf(v[w].x, q0.x, acc[1][w]);
                acc[1][w] = fmaf(v[w + 1].x, q0.y, acc[1][w]);
                acc[1][w] = fmaf(v[w + 2].x, q0.z, acc[1][w]);
                acc[1][w] = fmaf(v[w].y, q0.w, acc[1][w]);
                acc[1][w] = fmaf(v[w + 1].y, q1.x, acc[1][w]);
                acc[1][w] = fmaf(v[w + 2].y, q1.y, acc[1][w]);
                acc[1][w] = fmaf(v[w].z, q1.z, acc[1][w]);
                acc[1][w] = fmaf(v[w + 1].z, q1.w, acc[1][w]);
                acc[1][w] = fmaf(v[w + 2].z, q2.x, acc[1][w]);
                acc[1][w] = fmaf(v[w].w, q2.y, acc[1][w]);
                acc[1][w] = fmaf(v[w + 1].w, q2.z, acc[1][w]);
                acc[1][w] = fmaf(v[w + 2].w, q2.w, acc[1][w]);
            }
        }
#pragma unroll
        for (int i = 0; i < 4; i++) {
            __half2 h = __floats2half2_rn(tanh_fast(acc[0][i]), tanh_fast(acc[1][i]));
            g_Hh[((b * WPAD) + w0 + wl + i) * 32 + p] = *(uint32_t*)&h;
        }
    }
}

// ===========================================================================
// Kernel 2: dual GEMM mma.sync fp16 (3x k16 + 1x k8 = K56), ldmatrix loads,
//   64-w double-buffered smem stages (16 barriers instead of 31).
// ===========================================================================
#define ROWB 144    // 72 halves per smem row: conflict-free 16B phases

#define MMA_F16(C, A0, A1, A2, A3, B0, B1)                                  \
    asm volatile(                                                           \
        "mma.sync.aligned.m16n8k16.row.col.f32.f16.f16.f32 "                \
        "{%0,%1,%2,%3}, {%4,%5,%6,%7}, {%8,%9}, {%0,%1,%2,%3};"             \
        : "+f"((C)[0]), "+f"((C)[1]), "+f"((C)[2]), "+f"((C)[3])            \
        : "r"(A0), "r"(A1), "r"(A2), "r"(A3), "r"(B0), "r"(B1))

#define MMA_F16K8(C, A0, A1, B0)                                            \
    asm volatile(                                                           \
        "mma.sync.aligned.m16n8k8.row.col.f32.f16.f16.f32 "                 \
        "{%0,%1,%2,%3}, {%4,%5}, {%6}, {%0,%1,%2,%3};"                      \
        : "+f"((C)[0]), "+f"((C)[1]), "+f"((C)[2]), "+f"((C)[3])            \
        : "r"(A0), "r"(A1), "r"(B0))

#define LDSM_X4(R, A)                                                       \
    asm volatile("ldmatrix.sync.aligned.m8n8.x4.shared.b16 "                \
                 "{%0,%1,%2,%3}, [%4];"                                     \
                 : "=r"((R)[0]), "=r"((R)[1]), "=r"((R)[2]), "=r"((R)[3])   \
                 : "r"(A))

#define LDSM_X1(R, A)                                                       \
    asm volatile("ldmatrix.sync.aligned.m8n8.x1.shared.b16 {%0}, [%1];"     \
                 : "=r"(R) : "r"(A))

__device__ __forceinline__ uint32_t packh2(float lo, float hi) {
    __half2 h = __floats2half2_rn(lo, hi);
    return *(uint32_t*)&h;
}
__device__ __forceinline__ float ex2f(float x) {
    float y;
    asm("ex2.approx.f32 %0, %1;" : "=f"(y) : "f"(x));
    return y;
}
__device__ __forceinline__ uint32_t cvta_smem(const void* p) {
    uint32_t a;
    asm("{ .reg .u64 t; cvta.to.shared.u64 t, %1; cvt.u32.u64 %0, t; }"
        : "=r"(a) : "l"(p));
    return a;
}

__device__ __forceinline__ void compute_chunk(
    uint32_t sld, const uint32_t uA[3][4], const uint32_t oA[3][4],
    const uint32_t uA3[2], const uint32_t oA3[2],
    float dacc[2], float nacc[2]) {
    float sacc[4][4], pacc[4][4];
#pragma unroll
    for (int nf = 0; nf < 4; nf++)
#pragma unroll
        for (int c = 0; c < 4; c++) { sacc[nf][c] = 0.f; pacc[nf][c] = 0.f; }

#pragma unroll
    for (int ks = 0; ks < 3; ks++) {
        uint32_t b0v[4], b1v[4];
        LDSM_X4(b0v, sld + ks * 32);
        LDSM_X4(b1v, sld + ks * 32 + 16);
#pragma unroll
        for (int nf = 0; nf < 4; nf++) {
            MMA_F16(sacc[nf], uA[ks][0], uA[ks][1], uA[ks][2], uA[ks][3],
                    b0v[nf], b1v[nf]);
            MMA_F16(pacc[nf], oA[ks][0], oA[ks][1], oA[ks][2], oA[ks][3],
                    b0v[nf], b1v[nf]);
        }
    }
    {
        uint32_t bt[4];
        LDSM_X4(bt, sld + 96);
#pragma unroll
        for (int nf = 0; nf < 4; nf++) {
            MMA_F16K8(sacc[nf], uA3[0], uA3[1], bt[nf]);
            MMA_F16K8(pacc[nf], oA3[0], oA3[1], bt[nf]);
        }
    }
#pragma unroll
    for (int nf = 0; nf < 4; nf++)
#pragma unroll
        for (int c = 0; c < 4; c++) {
            float e = ex2f(sacc[nf][c]);
            int r = c >> 1;
            dacc[r] += e;
            nacc[r] = fmaf(e, pacc[nf][c], nacc[r]);
        }
}

__global__ __launch_bounds__(256, 2)
void attn_kernel(const float* __restrict__ u_w, const float* __restrict__ out_w,
                 const float* __restrict__ out_b, float* __restrict__ out) {
    __shared__ __align__(16) uint32_t Hs[2][64 * 36];   // 2 x 9216B (64 w-rows)

    const int tid  = threadIdx.x;
    const int b    = blockIdx.y;
    const int l0   = blockIdx.x * 128;
    const int lane = tid & 31;
    const int wid  = tid >> 5;
    const int gid  = lane >> 2;
    const int tig  = lane & 3;

    // ---- Hoisted A fragments: U pre-scaled by log2(e); K56
    const float LOG2E = 1.4426950408889634f;
    uint32_t uA[3][4], oA[3][4], uA3[2], oA3[2];
#pragma unroll
    for (int ks = 0; ks < 3; ks++)
#pragma unroll
        for (int h = 0; h < 2; h++) {
            int kp = ks * 8 + tig + h * 4;
#pragma unroll
            for (int mo = 0; mo < 2; mo++) {
                int l = l0 + wid * 16 + gid + mo * 8;
                float2 uv = make_float2(0.f, 0.f), ov = make_float2(0.f, 0.f);
                if (l < LL) {
                    uv = *(const float2*)&u_w[l * CC + 2 * kp];
                    ov = *(const float2*)&out_w[l * CC + 2 * kp];
                }
                uA[ks][h * 2 + mo] = packh2(uv.x * LOG2E, uv.y * LOG2E);
                oA[ks][h * 2 + mo] = packh2(ov.x, ov.y);
            }
        }
    {
        int kp = 24 + tig;   // k 48..55; only kp 24 (k48,49) non-zero
#pragma unroll
        for (int mo = 0; mo < 2; mo++) {
            int l = l0 + wid * 16 + gid + mo * 8;
            float u0 = 0.f, u1 = 0.f, o0 = 0.f, o1 = 0.f;
            if (l < LL && kp == 24) {
                u0 = u_w[l * CC + 48]; u1 = u_w[l * CC + 49];
                o0 = out_w[l * CC + 48]; o1 = out_w[l * CC + 49];
            }
            uA3[mo] = packh2(u0 * LOG2E, u1 * LOG2E);
            oA3[mo] = packh2(o0, o1);
        }
    }

    // ---- loader: 256 threads x 2 uint4 = 64 rows x 128B per stage
    const int lrow = tid >> 3, lseg = tid & 7;
    const uint32_t* gsrc = g_Hh + (b * WPAD + lrow) * 32 + lseg * 4;
    uint32_t s_base0 = cvta_smem(&Hs[0][0]);
    uint32_t s_base1 = cvta_smem(&Hs[1][0]);
    const uint32_t stoff0 = lrow * ROWB + lseg * 16;
    const uint32_t stoff1 = (lrow + 32) * ROWB + lseg * 16;

    // prologue: stage 0 -> buf0
    {
        uint4 v0 = *(const uint4*)gsrc;
        uint4 v1 = *(const uint4*)(gsrc + 32 * 32);
        asm volatile("st.shared.v4.b32 [%0], {%1,%2,%3,%4};"
                     :: "r"(s_base0 + stoff0), "r"(v0.x), "r"(v0.y), "r"(v0.z), "r"(v0.w));
        asm volatile("st.shared.v4.b32 [%0], {%1,%2,%3,%4};"
                     :: "r"(s_base0 + stoff1), "r"(v1.x), "r"(v1.y), "r"(v1.z), "r"(v1.w));
    }
    __syncthreads();

    float dacc[2] = {0.f, 0.f}, nacc[2] = {0.f, 0.f};

#pragma unroll 1
    for (int st = 0; st < 15; st++) {
        // prefetch stage st+1
        const uint32_t* gs = gsrc + (st + 1) * 64 * 32;
        uint4 p0 = *(const uint4*)gs;
        uint4 p1 = *(const uint4*)(gs + 32 * 32);

        const uint32_t sbase = (st & 1) ? s_base1 : s_base0;
        compute_chunk(sbase + lane * ROWB, uA, oA, uA3, oA3, dacc, nacc);
        compute_chunk(sbase + (32 + lane) * ROWB, uA, oA, uA3, oA3, dacc, nacc);

        const uint32_t dbase = (st & 1) ? s_base0 : s_base1;
        asm volatile("st.shared.v4.b32 [%0], {%1,%2,%3,%4};"
                     :: "r"(dbase + stoff0), "r"(p0.x), "r"(p0.y), "r"(p0.z), "r"(p0.w));
        asm volatile("st.shared.v4.b32 [%0], {%1,%2,%3,%4};"
                     :: "r"(dbase + stoff1), "r"(p1.x), "r"(p1.y), "r"(p1.z), "r"(p1.w));
        __syncthreads();
    }

    // ---- stage 15 (buf1): chunk w960..991 full; chunk w992..999 -> nf==0 only
    compute_chunk(s_base1 + lane * ROWB, uA, oA, uA3, oA3, dacc, nacc);
    {
        const uint32_t sld = s_base1 + (32 + (lane & 7)) * ROWB;
        float s4[4] = {0.f, 0.f, 0.f, 0.f}, p4[4] = {0.f, 0.f, 0.f, 0.f};
#pragma unroll
        for (int ks = 0; ks < 3; ks++) {
            uint32_t b0, b1;
            LDSM_X1(b0, sld + ks * 32);
            LDSM_X1(b1, sld + ks * 32 + 16);
            MMA_F16(s4, uA[ks][0], uA[ks][1], uA[ks][2], uA[ks][3], b0, b1);
            MMA_F16(p4, oA[ks][0], oA[ks][1], oA[ks][2], oA[ks][3], b0, b1);
        }
        uint32_t bt;
        LDSM_X1(bt, sld + 96);
        MMA_F16K8(s4, uA3[0], uA3[1], bt);
        MMA_F16K8(p4, oA3[0], oA3[1], bt);
#pragma unroll
        for (int c = 0; c < 4; c++) {
            float e = ex2f(s4[c]);
            int r = c >> 1;
            dacc[r] += e;
            nacc[r] = fmaf(e, p4[c], nacc[r]);
        }
    }

    // ---- reduce over 4 k-group lanes (different w), sigmoid, store
#pragma unroll
    for (int r = 0; r < 2; r++) {
        dacc[r] += __shfl_xor_sync(0xffffffffu, dacc[r], 1);
        dacc[r] += __shfl_xor_sync(0xffffffffu, dacc[r], 2);
        nacc[r] += __shfl_xor_sync(0xffffffffu, nacc[r], 1);
        nacc[r] += __shfl_xor_sync(0xffffffffu, nacc[r], 2);
    }
    if (tig == 0) {
#pragma unroll
        for (int r = 0; r < 2; r++) {
            int l = l0 + wid * 16 + gid + r * 8;
            if (l < LL) {
                float z = nacc[r] / dacc[r] + out_b[l];
                out[b * LL + l] = 1.f / (1.f + __expf(-z));
            }
        }
    }
}

// ===========================================================================
extern "C" void kernel_launch(void* const* d_in, const int* in_sizes, int n_in,
                              void* d_out, int out_size) {
    const int*   x       = (const int*)  d_in[0];
    const float* W_embed = (const float*)d_in[1];
    const float* conv_w  = (const float*)d_in[2];
    const float* conv_b  = (const float*)d_in[3];
    const float* u_w     = (const float*)d_in[4];
    const float* out_w   = (const float*)d_in[5];
    const float* out_b   = (const float*)d_in[6];
    float* out = (float*)d_out;

    dim3 cgrid(WLEN / CT_W, BB);          // (25, 8)
    conv_kernel<<<cgrid, 256>>>(x, W_embed, conv_w, conv_b);

    dim3 agrid((LL + 127) / 128, BB);     // (141, 8)
    attn_kernel<<<agrid, 256>>>(u_w, out_w, out_b, out);
}